// round 2
// baseline (speedup 1.0000x reference)
#include <cuda_runtime.h>

// CRF loss forward, B=512, N=1024, K=64, sm_100a.
// Linear-domain scan, 2 warps per chain (thread j owns one output state),
// register-resident exp(trans), f32x2 FMAs, one __syncthreads per step.

typedef unsigned long long ull;
#define FULLMASK 0xffffffffu

__device__ __forceinline__ void fma2(ull &d, ull a, ull b) {
    asm("fma.rn.f32x2 %0, %1, %2, %0;" : "+l"(d) : "l"(a), "l"(b));
}
__device__ __forceinline__ ull pack2(float x, float y) {
    ull r; asm("mov.b64 %0, {%1, %2};" : "=l"(r) : "f"(x), "f"(y)); return r;
}
__device__ __forceinline__ void unpack2(ull v, float &x, float &y) {
    asm("mov.b64 {%0, %1}, %2;" : "=f"(x), "=f"(y) : "l"(v));
}
__device__ __forceinline__ float ex2f(float x) {
    float r; asm("ex2.approx.f32 %0, %1;" : "=f"(r) : "f"(x)); return r;
}
__device__ __forceinline__ float lg2f(float x) {
    float r; asm("lg2.approx.f32 %0, %1;" : "=f"(r) : "f"(x)); return r;
}

__global__ __launch_bounds__(64) void crf_fwd_kernel(
    const float* __restrict__ y_pred,   // [B, N, K]
    const float* __restrict__ trans,    // [K, K]
    const int*   __restrict__ y_true,   // [B, N]
    float*       __restrict__ out)      // [B]
{
    constexpr int N = 1024;
    constexpr int K = 64;
    constexpr float LOG2E = 1.4426950408889634f;

    const int b   = blockIdx.x;
    const int tid = threadIdx.x;       // 0..63
    const int j   = tid;               // owned output state
    const int jp  = j ^ 32;            // mask partner channel
    const int w   = tid >> 5;          // warp within chain

    __shared__ __align__(16) float sh_a[2][K];  // double-buffered alpha
    __shared__ float sh_rmax[2];                // per-warp renorm max stash
    __shared__ float sh_sred[2];                // final sum partials
    __shared__ float sh_pred[2];                // final score partials

    // ---- E = exp(trans[:, j]) in registers, paired over i ----
    ull E[32];
    #pragma unroll
    for (int p = 0; p < 32; p++) {
        float t0 = __ldg(&trans[(2 * p)     * K + j]);
        float t1 = __ldg(&trans[(2 * p + 1) * K + j]);
        E[p] = pack2(ex2f(t0 * LOG2E), ex2f(t1 * LOG2E));
    }

    const float* emrow = y_pred + (size_t)b * N * K;
    const int*   ytrow = y_true + (size_t)b * N;

    // ---- t = 0 init ----
    float  pt = 0.f;
    double c2;
    int    ytprev;
    bool   pm;
    {
        float e0  = emrow[j];
        float e0p = emrow[jp];
        bool okl = (e0 > -1e6f) & (e0p > -1e6f);
        bool ok0 = __all_sync(FULLMASK, okl);
        float mv  = ok0 ? e0  : 0.f;
        float mvp = ok0 ? e0p : 0.f;
        float mx = fmaxf(mv, mvp);
        #pragma unroll
        for (int o = 16; o; o >>= 1) mx = fmaxf(mx, __shfl_xor_sync(FULLMASK, mx, o));
        sh_a[0][j] = ex2f((mv - mx) * LOG2E);
        c2 = (double)mx * 1.4426950408889634;   // log2-units scale
        ytprev = ytrow[0];
        if (ok0 && ytprev == j) pt += e0;
        pm = ok0;
    }
    __syncthreads();

    // ---- prefetch ring: 4 steps ahead ----
    float rem[4], remp[4]; int ryt[4];
    #pragma unroll
    for (int k = 0; k < 4; k++) {
        rem[k]  = __ldcs(&emrow[(1 + k) * K + j]);
        remp[k] = __ldcs(&emrow[(1 + k) * K + jp]);
        ryt[k]  = ytrow[1 + k];
    }

    float pend = 1.0f;   // deferred renorm divisor
    int   buf  = 0;

    for (int g = 0; g < 256; g++) {
        #pragma unroll
        for (int k = 0; k < 4; k++) {
            const int t = 1 + g * 4 + k;
            float em  = rem[k];
            float emp = remp[k];
            int   yt  = ryt[k];
            int tn = t + 4; tn = (tn > N - 1) ? (N - 1) : tn;
            rem[k]  = __ldcs(&emrow[tn * K + j]);
            remp[k] = __ldcs(&emrow[tn * K + jp]);
            ryt[k]  = ytrow[tn];

            if (t < N) {
                // fold the renorm max stashed by the previous k==3 step
                if (k == 0 && g > 0) {
                    float r = fmaxf(sh_rmax[0], sh_rmax[1]);
                    pend *= r;
                }

                bool okl = (em > -1e6f) & (emp > -1e6f);
                bool ok  = __all_sync(FULLMASK, okl);   // chain-uniform

                if (ok) {
                    // s_j = sum_i a[i] * E[i][j], 4 independent accumulators
                    const ulonglong2* ap = (const ulonglong2*)sh_a[buf];
                    ull a0 = 0ull, a1 = 0ull, a2 = 0ull, a3 = 0ull;
                    #pragma unroll
                    for (int q = 0; q < 8; q++) {
                        ulonglong2 v0 = ap[2 * q];
                        ulonglong2 v1 = ap[2 * q + 1];
                        fma2(a0, v0.x, E[4 * q]);
                        fma2(a1, v0.y, E[4 * q + 1]);
                        fma2(a2, v1.x, E[4 * q + 2]);
                        fma2(a3, v1.y, E[4 * q + 3]);
                    }
                    float x0, y0, x1, y1, x2, y2, x3, y3;
                    unpack2(a0, x0, y0); unpack2(a1, x1, y1);
                    unpack2(a2, x2, y2); unpack2(a3, x3, y3);
                    float s = ((x0 + x1) + (x2 + x3)) + ((y0 + y1) + (y2 + y3));
                    s *= ex2f(em * LOG2E);

                    if (pend != 1.0f) {
                        s *= __fdividef(1.0f, pend);
                        c2 += (double)lg2f(pend);
                        pend = 1.0f;
                    }

                    // target score: point + transition, one thread per chain
                    if (yt == j) {
                        pt += em;
                        if (pm) pt += __ldg(&trans[ytprev * K + j]);
                    }

                    sh_a[buf ^ 1][j] = s;

                    if (k == 3) {   // stash warp max for next step's fold
                        float r = s;
                        #pragma unroll
                        for (int o = 16; o; o >>= 1)
                            r = fmaxf(r, __shfl_xor_sync(FULLMASK, r, o));
                        if ((tid & 31) == 0) sh_rmax[w] = r;
                    }
                    pm = true;
                } else {
                    sh_a[buf ^ 1][j] = sh_a[buf][j];   // alpha unchanged
                    if (k == 3 && (tid & 31) == 0) sh_rmax[w] = 1.0f;
                    pm = false;
                }
                ytprev = yt;
                buf ^= 1;
                __syncthreads();
            }
        }
    }

    // ---- finalize: log_norm - target_score ----
    float ssum = sh_a[buf][j];
    float ptw  = pt;
    #pragma unroll
    for (int o = 16; o; o >>= 1) {
        ssum += __shfl_xor_sync(FULLMASK, ssum, o);
        ptw  += __shfl_xor_sync(FULLMASK, ptw,  o);
    }
    if ((tid & 31) == 0) { sh_sred[w] = ssum; sh_pred[w] = ptw; }
    __syncthreads();
    if (tid == 0) {
        float S  = sh_sred[0] + sh_sred[1];
        float PT = sh_pred[0] + sh_pred[1];
        double lognorm = (c2 + (double)lg2f(S)) * 0.6931471805599453;
        out[b] = (float)(lognorm - (double)PT);
    }
}

extern "C" void kernel_launch(void* const* d_in, const int* in_sizes, int n_in,
                              void* d_out, int out_size) {
    const float* y_pred = (const float*)d_in[0];
    const float* trans  = (const float*)d_in[1];
    const int*   y_true = (const int*)d_in[2];
    float* out = (float*)d_out;

    const int B = in_sizes[2] / 1024;   // 512
    crf_fwd_kernel<<<B, 64>>>(y_pred, trans, y_true, out);
}

// round 5
// speedup vs baseline: 1.1705x; 1.1705x over previous
#include <cuda_runtime.h>

// CRF loss forward, B=512, N=1024, K=64, sm_100a.
// One warp per chain (lane owns states 2l, 2l+1). Linear-domain scan with
// register-resident exp(trans), f32x2 FMAs, exp(emit) precomputed one step
// ahead, branchless step body. Renorm: R1-exact policy (warp-max every 4
// steps, divide, double c2 += lg2f(r)) — the numerics that measured 1.8e-7.

typedef unsigned long long ull;
#define FULLMASK 0xffffffffu

__device__ __forceinline__ void fma2(ull &d, ull a, ull b) {
    asm("fma.rn.f32x2 %0, %1, %2, %0;" : "+l"(d) : "l"(a), "l"(b));
}
__device__ __forceinline__ ull pack2(float x, float y) {
    ull r; asm("mov.b64 %0, {%1, %2};" : "=l"(r) : "f"(x), "f"(y)); return r;
}
__device__ __forceinline__ void unpack2(ull v, float &x, float &y) {
    asm("mov.b64 {%0, %1}, %2;" : "=f"(x), "=f"(y) : "l"(v));
}
__device__ __forceinline__ float ex2f(float x) {
    float r; asm("ex2.approx.f32 %0, %1;" : "=f"(r) : "f"(x)); return r;
}
__device__ __forceinline__ float lg2f(float x) {
    float r; asm("lg2.approx.f32 %0, %1;" : "=f"(r) : "f"(x)); return r;
}

__global__ __launch_bounds__(32) void crf_fwd_kernel(
    const float* __restrict__ y_pred,   // [B, N, K]
    const float* __restrict__ trans,    // [K, K]
    const int*   __restrict__ y_true,   // [B, N]
    float*       __restrict__ out)      // [B]
{
    constexpr int N = 1024;
    constexpr int K = 64;
    constexpr float LOG2E = 1.4426950408889634f;

    const int b    = blockIdx.x;
    const int lane = threadIdx.x;
    const int j0   = 2 * lane, j1 = j0 + 1;

    __shared__ ull sh_a[2][32];   // double-buffered alpha (64 floats as pairs)

    // ---- E = exp(trans) columns j0, j1 in registers, paired over i ----
    ull Er0[32], Er1[32];
    #pragma unroll
    for (int p = 0; p < 32; p++) {
        float t00 = __ldg(&trans[(2 * p)     * K + j0]);
        float t01 = __ldg(&trans[(2 * p + 1) * K + j0]);
        float t10 = __ldg(&trans[(2 * p)     * K + j1]);
        float t11 = __ldg(&trans[(2 * p + 1) * K + j1]);
        Er0[p] = pack2(ex2f(t00 * LOG2E), ex2f(t01 * LOG2E));
        Er1[p] = pack2(ex2f(t10 * LOG2E), ex2f(t11 * LOG2E));
    }

    const float2* emrow = (const float2*)y_pred + (size_t)b * N * 32;
    const int*    ytrow = y_true + (size_t)b * N;

    // ---- t = 0 init ----
    float  pt = 0.f;
    double c2;           // log2-units scale accumulator (R1-exact policy)
    int    ytprev;
    bool   pm;
    float  s0p, s1p;     // lane's own alpha pair (register copy)
    {
        float2 v = emrow[lane];
        bool okl = (v.x > -1e6f) & (v.y > -1e6f);
        bool ok0 = __all_sync(FULLMASK, okl);
        float mv0 = ok0 ? v.x : 0.f;
        float mv1 = ok0 ? v.y : 0.f;
        float mx = fmaxf(mv0, mv1);
        #pragma unroll
        for (int o = 16; o; o >>= 1) mx = fmaxf(mx, __shfl_xor_sync(FULLMASK, mx, o));
        s0p = ex2f((mv0 - mx) * LOG2E);
        s1p = ex2f((mv1 - mx) * LOG2E);
        c2 = (double)mx * 1.4426950408889634;
        ytprev = ytrow[0];
        if (ok0 && (ytprev >> 1) == lane) pt += (ytprev & 1) ? v.y : v.x;
        pm = ok0;
        sh_a[0][lane] = pack2(s0p, s1p);
    }
    __syncwarp();

    // ---- prefetch ring (depth 4) + exp-ahead ----
    float2 rem[4]; int ryt[4];
    #pragma unroll
    for (int k = 0; k < 4; k++) {
        rem[k] = __ldcs(&emrow[(1 + k) * 32 + lane]);
        ryt[k] = __ldg(&ytrow[1 + k]);
    }
    float2 enext;
    enext.x = ex2f(rem[0].x * LOG2E);
    enext.y = ex2f(rem[0].y * LOG2E);

    int buf = 0;

    // one scan step; SLOT = (T-1)&3 (compile-time constant); RENORM compile-time
    #define STEP(T, SLOT, RENORM)                                              \
    {                                                                          \
        const int t  = (T);                                                    \
        const int sl = (SLOT);                                                 \
        float em0 = rem[sl].x, em1 = rem[sl].y;                                \
        int   yt  = ryt[sl];                                                   \
        float2 ecur = enext;                                                   \
        float2 nxt  = rem[(sl + 1) & 3];                                       \
        enext.x = ex2f(nxt.x * LOG2E);                                         \
        enext.y = ex2f(nxt.y * LOG2E);                                         \
        int tf = t + 4; tf = (tf > N - 1) ? (N - 1) : tf;                      \
        rem[sl] = __ldcs(&emrow[tf * 32 + lane]);                              \
        ryt[sl] = __ldg(&ytrow[tf]);                                           \
        bool ok = __all_sync(FULLMASK, (em0 > -1e6f) & (em1 > -1e6f));         \
        const ulonglong2* ap = (const ulonglong2*)sh_a[buf];                   \
        ull A0 = 0ull, A1 = 0ull, B0 = 0ull, B1 = 0ull;                        \
        _Pragma("unroll")                                                      \
        for (int q = 0; q < 8; q++) {                                          \
            ulonglong2 v0 = ap[2 * q];                                         \
            ulonglong2 v1 = ap[2 * q + 1];                                     \
            fma2(A0, v0.x, Er0[4 * q]);                                        \
            fma2(B0, v0.x, Er1[4 * q]);                                        \
            fma2(A1, v0.y, Er0[4 * q + 1]);                                    \
            fma2(B1, v0.y, Er1[4 * q + 1]);                                    \
            fma2(A0, v1.x, Er0[4 * q + 2]);                                    \
            fma2(B0, v1.x, Er1[4 * q + 2]);                                    \
            fma2(A1, v1.y, Er0[4 * q + 3]);                                    \
            fma2(B1, v1.y, Er1[4 * q + 3]);                                    \
        }                                                                      \
        float xa, ya, xb, yb, xc, yc, xd, yd;                                  \
        unpack2(A0, xa, ya); unpack2(A1, xb, yb);                              \
        unpack2(B0, xc, yc); unpack2(B1, xd, yd);                              \
        float s0n = ((xa + xb) + (ya + yb)) * ecur.x;                          \
        float s1n = ((xc + xd) + (yc + yd)) * ecur.y;                          \
        float s0 = ok ? s0n : s0p;                                             \
        float s1 = ok ? s1n : s1p;                                             \
        if (ok && (yt >> 1) == lane) {                                         \
            pt += (yt & 1) ? em1 : em0;                                        \
            if (pm) pt += __ldg(&trans[ytprev * K + yt]);                      \
        }                                                                      \
        pm = ok; ytprev = yt;                                                  \
        if (RENORM) {                                                          \
            float r = fmaxf(s0, s1);                                           \
            _Pragma("unroll")                                                  \
            for (int o = 16; o; o >>= 1)                                       \
                r = fmaxf(r, __shfl_xor_sync(FULLMASK, r, o));                 \
            float inv = 1.0f / r;                                              \
            s0 *= inv; s1 *= inv;                                              \
            c2 += (double)lg2f(r);                                             \
        }                                                                      \
        s0p = s0; s1p = s1;                                                    \
        sh_a[buf ^ 1][lane] = pack2(s0, s1);                                   \
        buf ^= 1;                                                              \
        __syncwarp();                                                          \
    }

    // 255 groups of 4 (t = 1 .. 1020), renorm on last step of each group
    for (int g = 0; g < 255; g++) {
        const int tb = 1 + 4 * g;
        STEP(tb + 0, 0, false)
        STEP(tb + 1, 1, false)
        STEP(tb + 2, 2, false)
        STEP(tb + 3, 3, true)
    }
    // tail: t = 1021, 1022, 1023 (constant slots, no renorm)
    STEP(1021, 0, false)
    STEP(1022, 1, false)
    STEP(1023, 2, false)
    #undef STEP

    // ---- finalize: log_norm - target_score ----
    float ssum = s0p + s1p;
    #pragma unroll
    for (int o = 16; o; o >>= 1) {
        ssum += __shfl_xor_sync(FULLMASK, ssum, o);
        pt   += __shfl_xor_sync(FULLMASK, pt,   o);
    }
    if (lane == 0) {
        double lognorm = (c2 + (double)lg2f(ssum)) * 0.6931471805599453;
        out[b] = (float)(lognorm - (double)pt);
    }
}

extern "C" void kernel_launch(void* const* d_in, const int* in_sizes, int n_in,
                              void* d_out, int out_size) {
    const float* y_pred = (const float*)d_in[0];
    const float* trans  = (const float*)d_in[1];
    const int*   y_true = (const int*)d_in[2];
    float* out = (float*)d_out;

    const int B = in_sizes[2] / 1024;   // 512
    crf_fwd_kernel<<<B, 32>>>(y_pred, trans, y_true, out);
}